// round 15
// baseline (speedup 1.0000x reference)
#include <cuda_runtime.h>
#include <cuda_fp16.h>
#include <math.h>
#include <stdint.h>

// ---------------------------------------------------------------------------
// SphereConv: Chebyshev graph conv (K=5) + BatchNorm(train) + ReLU
// x[B=8, Fin=64, V=49152], E = 9V unsorted COO edges, weight[K=5,64,64],
// out[B,64,V] fp32.
//
// Conv bias cancels exactly inside training-mode BatchNorm -> never applied.
// T stored fp16. GEMM is native fp16 HMMA with W split fp16 hi+lo:
//   D = A*(Wh + Wl), dropped residual ~2^-22. A staged by raw cp.async.
// BN sum/sumsq partials are accumulated in the GEMM epilogue (no stats pass).
//
// SpMM: one warp = one vertex across ALL 8 batches (issue-bound fix, R12).
//
// State invariant across graph replays: g_cnt and g_dsum/g_dsq are ZERO at
// kernel_launch entry (static zero-init first call; re-zeroed by tail
// kernels every call).
// ---------------------------------------------------------------------------

namespace {
constexpr int V  = 49152;
constexpr int E  = 442368;
constexpr int B  = 8;
constexpr int F  = 64;
constexpr int K  = 5;
constexpr long long BVF = (long long)B * V * F;   // 25,165,824
constexpr long long VF  = (long long)V * F;       // 3,145,728
constexpr int NROWS = B * V;                      // 393,216
constexpr float EPS = 1e-5f;

constexpr int NB_COUNT = E / 256;                 // 1728
constexpr int NB_TRANS = (V / 32) * (F / 32) * B; // 24576

constexpr uint32_t TS = 144;                      // 128B row + 16B shift
constexpr uint32_t OFF_A  = 0;                    // 128 x 144 = 18432 B
constexpr uint32_t OFF_BH = OFF_A + 128 * TS;     // 64 x 144 = 9216 B
constexpr uint32_t OFF_BL = OFF_BH + 64 * TS;
constexpr uint32_t GEMM_SMEM = OFF_BL + 64 * TS;  // 36864 B
}

__device__ __half  g_Th[(size_t)K * BVF]; // T_0..T_4 fp16, [k][b][v][f]
__device__ float   g_acc[(size_t)BVF];    // pre-BN output, [b][c][v]
__device__ int     g_ptr[V + 1];
__device__ int     g_cnt[V];              // must be 0 at entry (invariant)
__device__ int2    g_edge[E];             // packed (col, val-bits)
__device__ uint2   g_Wh[5 * 1024];        // W^T hi fp16: [k][o(64)][i(64)]
__device__ uint2   g_Wl[5 * 1024];        // W^T lo fp16 (residual)
__device__ double  g_dsum[F];             // must be 0 at entry (invariant)
__device__ double  g_dsq[F];              // must be 0 at entry (invariant)
__device__ float   g_scale[F];
__device__ float   g_shift[F];

// ---------------- PTX helpers (all sm_80-compatible) ----------------

__device__ __forceinline__ uint32_t smem_u32(const void* p) {
    uint32_t a;
    asm("{ .reg .u64 t; cvta.to.shared.u64 t, %1; cvt.u32.u64 %0, t; }"
        : "=r"(a) : "l"(p));
    return a;
}

__device__ __forceinline__ void cp_async16(uint32_t saddr, const void* gaddr) {
    asm volatile("cp.async.cg.shared.global [%0], [%1], 16;"
                 :: "r"(saddr), "l"(gaddr));
}
__device__ __forceinline__ void cp_async_wait_all() {
    asm volatile("cp.async.commit_group;\ncp.async.wait_group 0;" ::: "memory");
}

__device__ __forceinline__ void ldsm_x4(uint32_t* r, uint32_t addr) {
    asm volatile("ldmatrix.sync.aligned.m8n8.x4.shared.b16 {%0,%1,%2,%3}, [%4];"
                 : "=r"(r[0]), "=r"(r[1]), "=r"(r[2]), "=r"(r[3]) : "r"(addr));
}
__device__ __forceinline__ void ldsm_x2(uint32_t* r, uint32_t addr) {
    asm volatile("ldmatrix.sync.aligned.m8n8.x2.shared.b16 {%0,%1}, [%2];"
                 : "=r"(r[0]), "=r"(r[1]) : "r"(addr));
}

__device__ __forceinline__ void mma16816h(float* c, const uint32_t* a,
                                          const uint32_t* b) {
    asm volatile(
        "mma.sync.aligned.m16n8k16.row.col.f32.f16.f16.f32 "
        "{%0,%1,%2,%3}, {%4,%5,%6,%7}, {%8,%9}, {%0,%1,%2,%3};"
        : "+f"(c[0]), "+f"(c[1]), "+f"(c[2]), "+f"(c[3])
        : "r"(a[0]), "r"(a[1]), "r"(a[2]), "r"(a[3]), "r"(b[0]), "r"(b[1]));
}

// ---------------- fused: COO row count + transpose x -> T0 fp16 ------------

__global__ void k_pre(const int* __restrict__ rows,
                      const float* __restrict__ x) {
    if (blockIdx.x < NB_COUNT) {
        int e = blockIdx.x * 256 + threadIdx.x;
        if (e < E) atomicAdd(&g_cnt[rows[e]], 1);
        return;
    }
    __shared__ float tile[32][33];
    int bid = blockIdx.x - NB_COUNT;
    int v0 = (bid % (V / 32)) * 32;
    int f0 = ((bid / (V / 32)) % (F / 32)) * 32;
    int b  = bid / ((V / 32) * (F / 32));
    int tx = threadIdx.x & 31;
    int ty = threadIdx.x >> 5;   // 0..7
    const float* xb = x + (size_t)b * F * V;
    #pragma unroll
    for (int j = 0; j < 32; j += 8)
        tile[ty + j][tx] = xb[(size_t)(f0 + ty + j) * V + v0 + tx];
    __syncthreads();
    __half* Tb = g_Th + (size_t)b * VF;
    #pragma unroll
    for (int j = 0; j < 32; j += 8)
        Tb[(size_t)(v0 + ty + j) * F + f0 + tx] = __float2half_rn(tile[tx][ty + j]);
}

// ---------------- CSR scan (parallel Hillis-Steele) + scatter --------------

__global__ void k_scan() {
    __shared__ int part[1024];
    int t = threadIdx.x;
    const int CH = V / 1024;  // 48
    int base = t * CH;
    int s = 0;
    for (int i = 0; i < CH; i++) s += g_cnt[base + i];
    part[t] = s;
    __syncthreads();
    // inclusive scan over 1024 partials
    #pragma unroll
    for (int off = 1; off < 1024; off <<= 1) {
        int v = (t >= off) ? part[t - off] : 0;
        __syncthreads();
        part[t] += v;
        __syncthreads();
    }
    int run = part[t] - s;   // exclusive prefix for this thread's chunk
    for (int i = 0; i < CH; i++) {
        g_ptr[base + i] = run;
        run += g_cnt[base + i];
        g_cnt[base + i] = 0;   // re-zero for scatter cursors
    }
    if (t == 1023) g_ptr[V] = E;
}

__global__ void k_scatter(const int* __restrict__ rows,
                          const int* __restrict__ cols,
                          const float* __restrict__ vals) {
    int e = blockIdx.x * 256 + threadIdx.x;
    if (e < E) {
        int r = rows[e];
        int p = g_ptr[r] + atomicAdd(&g_cnt[r], 1);
        g_edge[p] = make_int2(cols[e], __float_as_int(vals[e]));
    }
}

// ---------------- W prep: weight[k][i][o] -> W^T fp16 hi/lo [k][o][i] ------

__global__ void k_wprep(const float* __restrict__ weight) {
    int idx = blockIdx.x * 256 + threadIdx.x;   // 5120 uint2 slots
    if (idx >= 5 * 1024) return;
    int k   = idx >> 10;
    int rem = idx & 1023;
    int o   = rem >> 4;
    int i0  = (rem & 15) * 4;
    const float* Wk = weight + k * 4096;
    float v0 = Wk[(i0 + 0) * 64 + o];
    float v1 = Wk[(i0 + 1) * 64 + o];
    float v2 = Wk[(i0 + 2) * 64 + o];
    float v3 = Wk[(i0 + 3) * 64 + o];
    __half2 h01 = __floats2half2_rn(v0, v1);
    __half2 h23 = __floats2half2_rn(v2, v3);
    float l0 = v0 - __half2float(__low2half(h01));
    float l1 = v1 - __half2float(__high2half(h01));
    float l2 = v2 - __half2float(__low2half(h23));
    float l3 = v3 - __half2float(__high2half(h23));
    __half2 lo01 = __floats2half2_rn(l0, l1);
    __half2 lo23 = __floats2half2_rn(l2, l3);
    g_Wh[idx] = make_uint2(*reinterpret_cast<uint32_t*>(&h01),
                           *reinterpret_cast<uint32_t*>(&h23));
    g_Wl[idx] = make_uint2(*reinterpret_cast<uint32_t*>(&lo01),
                           *reinterpret_cast<uint32_t*>(&lo23));
}

// ---------------- SpMM: T_ko = L(T_kp)  (or 2*L(T_kp) - T_kpp) -------------
// One warp = one vertex, ALL 8 batches: edge load + address math amortized.

__global__ void __launch_bounds__(256)
k_spmm(int kp, int kpp, int ko, int first) {
    int lane = threadIdx.x & 31;
    int wid  = threadIdx.x >> 5;
    int v = blockIdx.x * 8 + wid;
    const __half* __restrict__ Tp = g_Th + (size_t)kp * BVF;
    int beg = g_ptr[v], end = g_ptr[v + 1];
    float ax[8], ay[8];
    #pragma unroll
    for (int b = 0; b < 8; b++) { ax[b] = 0.f; ay[b] = 0.f; }
    int fo = lane * 2;
    for (int e = beg; e < end; e++) {
        int2 ed = g_edge[e];                  // uniform (broadcast) load
        float w = __int_as_float(ed.y);
        const __half* p = Tp + (size_t)ed.x * F + fo;
        #pragma unroll
        for (int b = 0; b < 8; b++) {
            float2 t = __half22float2(
                *reinterpret_cast<const __half2*>(p + (size_t)b * VF));
            ax[b] = fmaf(w, t.x, ax[b]);
            ay[b] = fmaf(w, t.y, ay[b]);
        }
    }
    size_t oi0 = (size_t)v * F + fo;
    if (first) {
        #pragma unroll
        for (int b = 0; b < 8; b++) {
            *reinterpret_cast<__half2*>(g_Th + (size_t)ko * BVF + (size_t)b * VF + oi0) =
                __floats2half2_rn(ax[b], ay[b]);
        }
    } else {
        const __half* Tpp = g_Th + (size_t)kpp * BVF;
        #pragma unroll
        for (int b = 0; b < 8; b++) {
            float2 p2 = __half22float2(
                *reinterpret_cast<const __half2*>(Tpp + (size_t)b * VF + oi0));
            *reinterpret_cast<__half2*>(g_Th + (size_t)ko * BVF + (size_t)b * VF + oi0) =
                __floats2half2_rn(2.f * ax[b] - p2.x, 2.f * ay[b] - p2.y);
        }
    }
}

// ---------------- HMMA GEMM (fp16 x2) + fused BN partials ------------------
// CTA tile 128(M) x 64(N); 8 warps, each 16 rows x 64 cols.
// A staged by raw cp.async (fp16 native). D += A*Wh + A*Wl, fp32 accum.
// Epilogue: store channel-major AND accumulate per-channel sum/sumsq.

__global__ void __launch_bounds__(256)
k_gemm() {
    extern __shared__ char smem[];
    __shared__ float rsum[64];
    __shared__ float rsq[64];
    uint32_t sb = smem_u32(smem);
    int tid  = threadIdx.x;
    int warp = tid >> 5;
    int lane = tid & 31;

    long long r0 = (long long)blockIdx.x * 128;

    float acc[8][4];
    #pragma unroll
    for (int g = 0; g < 8; g++)
        #pragma unroll
        for (int j = 0; j < 4; j++) acc[g][j] = 0.f;

    // ldmatrix source addresses (per-lane, fixed across k-chunks)
    int at    = lane >> 3;           // 0..3
    int arow  = warp * 16 + (lane & 7) + (at & 1) * 8;
    uint32_t akoff = (uint32_t)(at >> 1) * 16;     // +8 halves = +16 B
    uint32_t aaddr = sb + OFF_A + arow * TS + akoff;
    int bl    = lane & 15;
    int btile = bl >> 3;
    int brow  = bl & 7;
    uint32_t bkoff = (uint32_t)btile * 16;

    if (tid < 64) { rsum[tid] = 0.f; rsq[tid] = 0.f; }

    for (int k = 0; k < K; k++) {
        // --- stage A tile: raw fp16 copy, 1024 x 16B chunks, cp.async ---
        const char* Ak = reinterpret_cast<const char*>(
            g_Th + (size_t)k * BVF + (size_t)r0 * 64);
        #pragma unroll
        for (int q = 0; q < 4; q++) {
            int idx = q * 256 + tid;          // 0..1023
            int r   = idx >> 3;               // row 0..127
            int c   = idx & 7;                // 16B chunk 0..7
            cp_async16(sb + OFF_A + (uint32_t)r * TS + (uint32_t)c * 16,
                       Ak + (size_t)r * 128 + c * 16);
        }
        // --- stage B tiles: Wh/Wl fp16, 512 x 16B chunks each ---
        {
            int idx = tid;                    // 0..255 -> 2 chunks each of Wh,Wl
            const char* WhK = reinterpret_cast<const char*>(g_Wh + k * 1024);
            const char* WlK = reinterpret_cast<const char*>(g_Wl + k * 1024);
            #pragma unroll
            for (int q = 0; q < 2; q++) {
                int i2 = q * 256 + idx;       // 0..511
                int r  = i2 >> 3;
                int c  = i2 & 7;
                uint32_t so = (uint32_t)r * TS + (uint32_t)c * 16;
                size_t  go = (size_t)r * 128 + c * 16;
                cp_async16(sb + OFF_BH + so, WhK + go);
                cp_async16(sb + OFF_BL + so, WlK + go);
            }
        }
        cp_async_wait_all();
        __syncthreads();

        #pragma unroll
        for (int k16 = 0; k16 < 4; k16++) {
            uint32_t kb = (uint32_t)k16 * 32;  // 16 halves = 32 B per k16 step
            uint32_t a[4];
            ldsm_x4(a, aaddr + kb);
            #pragma unroll
            for (int g = 0; g < 8; g++) {
                uint32_t boff = (uint32_t)(g * 8 + brow) * TS + kb + bkoff;
                uint32_t bh[2], blo[2];
                ldsm_x2(bh,  sb + OFF_BH + boff);
                ldsm_x2(blo, sb + OFF_BL + boff);
                mma16816h(acc[g], a, bh);
                mma16816h(acc[g], a, blo);
            }
        }
        __syncthreads();   // compute done before next k overwrites SMEM
    }

    // Epilogue: store channel-major + accumulate BN partials.
    // Thread holds rows (v0, v0+8), cols c0 = g*8 + 2*(lane&3) + {0,1}.
    long long rowb = r0 + warp * 16;
    int b  = (int)(rowb / V);          // constant per CTA (V % 128 == 0)
    int v0 = (int)(rowb % V) + (lane >> 2);
    float* ap = g_acc + (size_t)b * 64 * V;
    #pragma unroll
    for (int g = 0; g < 8; g++) {
        int c0 = g * 8 + 2 * (lane & 3);
        float a0 = acc[g][0], a1 = acc[g][1], a2 = acc[g][2], a3 = acc[g][3];
        ap[(size_t)c0 * V + v0]           = a0;
        ap[(size_t)(c0 + 1) * V + v0]     = a1;
        ap[(size_t)c0 * V + v0 + 8]       = a2;
        ap[(size_t)(c0 + 1) * V + v0 + 8] = a3;
        atomicAdd(&rsum[c0],     a0 + a2);
        atomicAdd(&rsum[c0 + 1], a1 + a3);
        atomicAdd(&rsq[c0],      a0 * a0 + a2 * a2);
        atomicAdd(&rsq[c0 + 1],  a1 * a1 + a3 * a3);
    }
    __syncthreads();
    if (tid < 64) {
        atomicAdd(&g_dsum[tid], (double)rsum[tid]);
        atomicAdd(&g_dsq[tid],  (double)rsq[tid]);
    }
}

// ---------------- BN finalize (+ re-zero stats for next replay) ----------

__global__ void k_bnfin(const float* __restrict__ gamma,
                        const float* __restrict__ beta) {
    int o = threadIdx.x;
    double n = (double)NROWS;
    double mean = g_dsum[o] / n;
    double var  = g_dsq[o] / n - mean * mean;
    float sc = gamma[o] * rsqrtf((float)var + EPS);
    g_scale[o] = sc;
    g_shift[o] = beta[o] - (float)mean * sc;
    g_dsum[o] = 0.0;   // restore invariant for next graph replay
    g_dsq[o]  = 0.0;
}

// ---------------- normalize + ReLU (+ re-zero g_cnt for next replay) ------

__global__ void __launch_bounds__(256)
k_final(float* __restrict__ out) {
    int gtid = blockIdx.x * 256 + threadIdx.x;
    if (gtid < V) g_cnt[gtid] = 0;   // restore invariant (grid covers V)
    long long n4 = BVF / 4;
    for (long long i4 = gtid; i4 < n4; i4 += (long long)gridDim.x * 256) {
        long long i = i4 * 4;
        int c = (int)((i / V) & 63);
        float sc = g_scale[c], sh = g_shift[c];
        float4 v = *reinterpret_cast<const float4*>(g_acc + i);
        v.x = fmaxf(fmaf(v.x, sc, sh), 0.f);
        v.y = fmaxf(fmaf(v.y, sc, sh), 0.f);
        v.z = fmaxf(fmaf(v.z, sc, sh), 0.f);
        v.w = fmaxf(fmaf(v.w, sc, sh), 0.f);
        *reinterpret_cast<float4*>(out + i) = v;
    }
}

// ---------------- launch ----------------

extern "C" void kernel_launch(void* const* d_in, const int* in_sizes, int n_in,
                              void* d_out, int out_size) {
    const float* x      = (const float*)d_in[0];
    const int*   rows   = (const int*)  d_in[1];
    const int*   cols   = (const int*)  d_in[2];
    const float* vals   = (const float*)d_in[3];
    const float* weight = (const float*)d_in[4];
    const float* gamma  = (const float*)d_in[6];
    const float* beta   = (const float*)d_in[7];
    float* out = (float*)d_out;

    cudaFuncSetAttribute(k_gemm, cudaFuncAttributeMaxDynamicSharedMemorySize,
                         GEMM_SMEM);

    k_pre<<<NB_COUNT + NB_TRANS, 256>>>(rows, x);          // 0: count+transpose
    k_scan<<<1, 1024>>>();                                 // 1
    k_scatter<<<E / 256, 256>>>(rows, cols, vals);         // 2

    k_spmm<<<V / 8, 256>>>(0, 0, 1, 1);   // 3  <- ncu-profiled slot
    k_spmm<<<V / 8, 256>>>(1, 0, 2, 0);   // 4
    k_spmm<<<V / 8, 256>>>(2, 1, 3, 0);   // 5
    k_spmm<<<V / 8, 256>>>(3, 2, 4, 0);   // 6

    k_wprep<<<20, 256>>>(weight);                          // 7
    k_gemm<<<NROWS / 128, 256, GEMM_SMEM>>>();             // 8 (+BN partials)

    k_bnfin<<<1, 64>>>(gamma, beta);                       // 9
    k_final<<<4096, 256>>>(out);                           // 10
}

// round 16
// speedup vs baseline: 1.1882x; 1.1882x over previous
#include <cuda_runtime.h>
#include <cuda_fp16.h>
#include <math.h>
#include <stdint.h>

// ---------------------------------------------------------------------------
// SphereConv: Chebyshev graph conv (K=5) + BatchNorm(train) + ReLU
// x[B=8, Fin=64, V=49152], E = 9V unsorted COO edges, weight[K=5,64,64],
// out[B,64,V] fp32.
//
// Conv bias cancels exactly inside training-mode BatchNorm -> never applied.
// T stored fp16. GEMM is native fp16 HMMA with W split fp16 hi+lo:
//   D = A*(Wh + Wl), dropped residual ~2^-22. A staged by raw cp.async.
// BN stats are a SEPARATE streaming pass (k_stats): fusing them into the
// GEMM epilogue regressed +100us from shared/global atomic contention (R15).
//
// SpMM: one warp = one vertex across ALL 8 batches (issue-bound fix, R12).
//
// State invariant across graph replays: g_cnt and g_dsum/g_dsq are ZERO at
// kernel_launch entry (static zero-init first call; re-zeroed by tail
// kernels every call).
// ---------------------------------------------------------------------------

namespace {
constexpr int V  = 49152;
constexpr int E  = 442368;
constexpr int B  = 8;
constexpr int F  = 64;
constexpr int K  = 5;
constexpr long long BVF = (long long)B * V * F;   // 25,165,824
constexpr long long VF  = (long long)V * F;       // 3,145,728
constexpr int NROWS = B * V;                      // 393,216
constexpr float EPS = 1e-5f;

constexpr int NB_COUNT = E / 256;                 // 1728
constexpr int NB_TRANS = (V / 32) * (F / 32) * B; // 24576

constexpr uint32_t TS = 144;                      // 128B row + 16B shift
constexpr uint32_t OFF_A  = 0;                    // 128 x 144 = 18432 B
constexpr uint32_t OFF_BH = OFF_A + 128 * TS;     // 64 x 144 = 9216 B
constexpr uint32_t OFF_BL = OFF_BH + 64 * TS;
constexpr uint32_t GEMM_SMEM = OFF_BL + 64 * TS;  // 36864 B
}

__device__ __half  g_Th[(size_t)K * BVF]; // T_0..T_4 fp16, [k][b][v][f]
__device__ float   g_acc[(size_t)BVF];    // pre-BN output, [b][c][v]
__device__ int     g_ptr[V + 1];
__device__ int     g_cnt[V];              // must be 0 at entry (invariant)
__device__ int2    g_edge[E];             // packed (col, val-bits)
__device__ uint2   g_Wh[5 * 1024];        // W^T hi fp16: [k][o(64)][i(64)]
__device__ uint2   g_Wl[5 * 1024];        // W^T lo fp16 (residual)
__device__ double  g_dsum[F];             // must be 0 at entry (invariant)
__device__ double  g_dsq[F];              // must be 0 at entry (invariant)
__device__ float   g_scale[F];
__device__ float   g_shift[F];

// ---------------- PTX helpers (all sm_80-compatible) ----------------

__device__ __forceinline__ uint32_t smem_u32(const void* p) {
    uint32_t a;
    asm("{ .reg .u64 t; cvta.to.shared.u64 t, %1; cvt.u32.u64 %0, t; }"
        : "=r"(a) : "l"(p));
    return a;
}

__device__ __forceinline__ void cp_async16(uint32_t saddr, const void* gaddr) {
    asm volatile("cp.async.cg.shared.global [%0], [%1], 16;"
                 :: "r"(saddr), "l"(gaddr));
}
__device__ __forceinline__ void cp_async_wait_all() {
    asm volatile("cp.async.commit_group;\ncp.async.wait_group 0;" ::: "memory");
}

__device__ __forceinline__ void ldsm_x4(uint32_t* r, uint32_t addr) {
    asm volatile("ldmatrix.sync.aligned.m8n8.x4.shared.b16 {%0,%1,%2,%3}, [%4];"
                 : "=r"(r[0]), "=r"(r[1]), "=r"(r[2]), "=r"(r[3]) : "r"(addr));
}
__device__ __forceinline__ void ldsm_x2(uint32_t* r, uint32_t addr) {
    asm volatile("ldmatrix.sync.aligned.m8n8.x2.shared.b16 {%0,%1}, [%2];"
                 : "=r"(r[0]), "=r"(r[1]) : "r"(addr));
}

__device__ __forceinline__ void mma16816h(float* c, const uint32_t* a,
                                          const uint32_t* b) {
    asm volatile(
        "mma.sync.aligned.m16n8k16.row.col.f32.f16.f16.f32 "
        "{%0,%1,%2,%3}, {%4,%5,%6,%7}, {%8,%9}, {%0,%1,%2,%3};"
        : "+f"(c[0]), "+f"(c[1]), "+f"(c[2]), "+f"(c[3])
        : "r"(a[0]), "r"(a[1]), "r"(a[2]), "r"(a[3]), "r"(b[0]), "r"(b[1]));
}

// ---------------- fused: COO row count + transpose x -> T0 fp16 ------------

__global__ void k_pre(const int* __restrict__ rows,
                      const float* __restrict__ x) {
    if (blockIdx.x < NB_COUNT) {
        int e = blockIdx.x * 256 + threadIdx.x;
        if (e < E) atomicAdd(&g_cnt[rows[e]], 1);
        return;
    }
    __shared__ float tile[32][33];
    int bid = blockIdx.x - NB_COUNT;
    int v0 = (bid % (V / 32)) * 32;
    int f0 = ((bid / (V / 32)) % (F / 32)) * 32;
    int b  = bid / ((V / 32) * (F / 32));
    int tx = threadIdx.x & 31;
    int ty = threadIdx.x >> 5;   // 0..7
    const float* xb = x + (size_t)b * F * V;
    #pragma unroll
    for (int j = 0; j < 32; j += 8)
        tile[ty + j][tx] = xb[(size_t)(f0 + ty + j) * V + v0 + tx];
    __syncthreads();
    __half* Tb = g_Th + (size_t)b * VF;
    #pragma unroll
    for (int j = 0; j < 32; j += 8)
        Tb[(size_t)(v0 + ty + j) * F + f0 + tx] = __float2half_rn(tile[tx][ty + j]);
}

// ---------------- CSR scan (parallel Hillis-Steele) + scatter --------------

__global__ void k_scan() {
    __shared__ int part[1024];
    int t = threadIdx.x;
    const int CH = V / 1024;  // 48
    int base = t * CH;
    int s = 0;
    for (int i = 0; i < CH; i++) s += g_cnt[base + i];
    part[t] = s;
    __syncthreads();
    // inclusive scan over 1024 partials
    #pragma unroll
    for (int off = 1; off < 1024; off <<= 1) {
        int v = (t >= off) ? part[t - off] : 0;
        __syncthreads();
        part[t] += v;
        __syncthreads();
    }
    int run = part[t] - s;   // exclusive prefix for this thread's chunk
    for (int i = 0; i < CH; i++) {
        g_ptr[base + i] = run;
        run += g_cnt[base + i];
        g_cnt[base + i] = 0;   // re-zero for scatter cursors
    }
    if (t == 1023) g_ptr[V] = E;
}

__global__ void k_scatter(const int* __restrict__ rows,
                          const int* __restrict__ cols,
                          const float* __restrict__ vals) {
    int e = blockIdx.x * 256 + threadIdx.x;
    if (e < E) {
        int r = rows[e];
        int p = g_ptr[r] + atomicAdd(&g_cnt[r], 1);
        g_edge[p] = make_int2(cols[e], __float_as_int(vals[e]));
    }
}

// ---------------- W prep: weight[k][i][o] -> W^T fp16 hi/lo [k][o][i] ------

__global__ void k_wprep(const float* __restrict__ weight) {
    int idx = blockIdx.x * 256 + threadIdx.x;   // 5120 uint2 slots
    if (idx >= 5 * 1024) return;
    int k   = idx >> 10;
    int rem = idx & 1023;
    int o   = rem >> 4;
    int i0  = (rem & 15) * 4;
    const float* Wk = weight + k * 4096;
    float v0 = Wk[(i0 + 0) * 64 + o];
    float v1 = Wk[(i0 + 1) * 64 + o];
    float v2 = Wk[(i0 + 2) * 64 + o];
    float v3 = Wk[(i0 + 3) * 64 + o];
    __half2 h01 = __floats2half2_rn(v0, v1);
    __half2 h23 = __floats2half2_rn(v2, v3);
    float l0 = v0 - __half2float(__low2half(h01));
    float l1 = v1 - __half2float(__high2half(h01));
    float l2 = v2 - __half2float(__low2half(h23));
    float l3 = v3 - __half2float(__high2half(h23));
    __half2 lo01 = __floats2half2_rn(l0, l1);
    __half2 lo23 = __floats2half2_rn(l2, l3);
    g_Wh[idx] = make_uint2(*reinterpret_cast<uint32_t*>(&h01),
                           *reinterpret_cast<uint32_t*>(&h23));
    g_Wl[idx] = make_uint2(*reinterpret_cast<uint32_t*>(&lo01),
                           *reinterpret_cast<uint32_t*>(&lo23));
}

// ---------------- SpMM: T_ko = L(T_kp)  (or 2*L(T_kp) - T_kpp) -------------
// One warp = one vertex, ALL 8 batches: edge load + address math amortized.

__global__ void __launch_bounds__(256)
k_spmm(int kp, int kpp, int ko, int first) {
    int lane = threadIdx.x & 31;
    int wid  = threadIdx.x >> 5;
    int v = blockIdx.x * 8 + wid;
    const __half* __restrict__ Tp = g_Th + (size_t)kp * BVF;
    int beg = g_ptr[v], end = g_ptr[v + 1];
    float ax[8], ay[8];
    #pragma unroll
    for (int b = 0; b < 8; b++) { ax[b] = 0.f; ay[b] = 0.f; }
    int fo = lane * 2;
    for (int e = beg; e < end; e++) {
        int2 ed = g_edge[e];                  // uniform (broadcast) load
        float w = __int_as_float(ed.y);
        const __half* p = Tp + (size_t)ed.x * F + fo;
        #pragma unroll
        for (int b = 0; b < 8; b++) {
            float2 t = __half22float2(
                *reinterpret_cast<const __half2*>(p + (size_t)b * VF));
            ax[b] = fmaf(w, t.x, ax[b]);
            ay[b] = fmaf(w, t.y, ay[b]);
        }
    }
    size_t oi0 = (size_t)v * F + fo;
    if (first) {
        #pragma unroll
        for (int b = 0; b < 8; b++) {
            *reinterpret_cast<__half2*>(g_Th + (size_t)ko * BVF + (size_t)b * VF + oi0) =
                __floats2half2_rn(ax[b], ay[b]);
        }
    } else {
        const __half* Tpp = g_Th + (size_t)kpp * BVF;
        #pragma unroll
        for (int b = 0; b < 8; b++) {
            float2 p2 = __half22float2(
                *reinterpret_cast<const __half2*>(Tpp + (size_t)b * VF + oi0));
            *reinterpret_cast<__half2*>(g_Th + (size_t)ko * BVF + (size_t)b * VF + oi0) =
                __floats2half2_rn(2.f * ax[b] - p2.x, 2.f * ay[b] - p2.y);
        }
    }
}

// ---------------- HMMA GEMM (fp16 x2): acc[b][c][v] = sum_k T_k @ W_k ------
// CTA tile 128(M) x 64(N); 8 warps, each 16 rows x 64 cols.
// A staged by raw cp.async (fp16 native). D += A*Wh + A*Wl, fp32 accum.

__global__ void __launch_bounds__(256)
k_gemm() {
    extern __shared__ char smem[];
    uint32_t sb = smem_u32(smem);
    int tid  = threadIdx.x;
    int warp = tid >> 5;
    int lane = tid & 31;

    long long r0 = (long long)blockIdx.x * 128;

    float acc[8][4];
    #pragma unroll
    for (int g = 0; g < 8; g++)
        #pragma unroll
        for (int j = 0; j < 4; j++) acc[g][j] = 0.f;

    // ldmatrix source addresses (per-lane, fixed across k-chunks)
    int at    = lane >> 3;           // 0..3
    int arow  = warp * 16 + (lane & 7) + (at & 1) * 8;
    uint32_t akoff = (uint32_t)(at >> 1) * 16;     // +8 halves = +16 B
    uint32_t aaddr = sb + OFF_A + arow * TS + akoff;
    int bl    = lane & 15;
    int btile = bl >> 3;
    int brow  = bl & 7;
    uint32_t bkoff = (uint32_t)btile * 16;

    for (int k = 0; k < K; k++) {
        // --- stage A tile: raw fp16 copy, 1024 x 16B chunks, cp.async ---
        const char* Ak = reinterpret_cast<const char*>(
            g_Th + (size_t)k * BVF + (size_t)r0 * 64);
        #pragma unroll
        for (int q = 0; q < 4; q++) {
            int idx = q * 256 + tid;          // 0..1023
            int r   = idx >> 3;               // row 0..127
            int c   = idx & 7;                // 16B chunk 0..7
            cp_async16(sb + OFF_A + (uint32_t)r * TS + (uint32_t)c * 16,
                       Ak + (size_t)r * 128 + c * 16);
        }
        // --- stage B tiles: Wh/Wl fp16, 512 x 16B chunks each ---
        {
            int idx = tid;                    // 0..255 -> 2 chunks each of Wh,Wl
            const char* WhK = reinterpret_cast<const char*>(g_Wh + k * 1024);
            const char* WlK = reinterpret_cast<const char*>(g_Wl + k * 1024);
            #pragma unroll
            for (int q = 0; q < 2; q++) {
                int i2 = q * 256 + idx;       // 0..511
                int r  = i2 >> 3;
                int c  = i2 & 7;
                uint32_t so = (uint32_t)r * TS + (uint32_t)c * 16;
                size_t  go = (size_t)r * 128 + c * 16;
                cp_async16(sb + OFF_BH + so, WhK + go);
                cp_async16(sb + OFF_BL + so, WlK + go);
            }
        }
        cp_async_wait_all();
        __syncthreads();

        #pragma unroll
        for (int k16 = 0; k16 < 4; k16++) {
            uint32_t kb = (uint32_t)k16 * 32;  // 16 halves = 32 B per k16 step
            uint32_t a[4];
            ldsm_x4(a, aaddr + kb);
            #pragma unroll
            for (int g = 0; g < 8; g++) {
                uint32_t boff = (uint32_t)(g * 8 + brow) * TS + kb + bkoff;
                uint32_t bh[2], blo[2];
                ldsm_x2(bh,  sb + OFF_BH + boff);
                ldsm_x2(blo, sb + OFF_BL + boff);
                mma16816h(acc[g], a, bh);
                mma16816h(acc[g], a, blo);
            }
        }
        __syncthreads();   // compute done before next k overwrites SMEM
    }

    // Epilogue: store channel-major. Thread holds rows (v0, v0+8), cols
    // g*8 + 2*(lane&3) + {0,1}.
    long long rowb = r0 + warp * 16;
    int b  = (int)(rowb / V);          // constant per CTA (V % 128 == 0)
    int v0 = (int)(rowb % V) + (lane >> 2);
    float* ap = g_acc + (size_t)b * 64 * V;
    #pragma unroll
    for (int g = 0; g < 8; g++) {
        int c0 = g * 8 + 2 * (lane & 3);
        ap[(size_t)c0 * V + v0]           = acc[g][0];
        ap[(size_t)(c0 + 1) * V + v0]     = acc[g][1];
        ap[(size_t)c0 * V + v0 + 8]       = acc[g][2];
        ap[(size_t)(c0 + 1) * V + v0 + 8] = acc[g][3];
    }
}

// ---------------- BN stats over g_acc [b][c][v] (streaming pass) ----------

__global__ void __launch_bounds__(256)
k_stats() {
    __shared__ float ssum[8], ssq[8];
    int b = blockIdx.x >> 6;
    int c = blockIdx.x & 63;
    const float* p = g_acc + ((size_t)b * 64 + c) * V;
    int tid = threadIdx.x;
    float s = 0.f, s2 = 0.f;
    for (int i = tid * 4; i < V; i += 256 * 4) {
        float4 v = *reinterpret_cast<const float4*>(p + i);
        s  += v.x + v.y + v.z + v.w;
        s2 += v.x * v.x + v.y * v.y + v.z * v.z + v.w * v.w;
    }
    #pragma unroll
    for (int o = 16; o > 0; o >>= 1) {
        s  += __shfl_xor_sync(0xffffffffu, s,  o);
        s2 += __shfl_xor_sync(0xffffffffu, s2, o);
    }
    if ((tid & 31) == 0) { ssum[tid >> 5] = s; ssq[tid >> 5] = s2; }
    __syncthreads();
    if (tid == 0) {
        float ts = 0.f, tq = 0.f;
        #pragma unroll
        for (int w = 0; w < 8; w++) { ts += ssum[w]; tq += ssq[w]; }
        atomicAdd(&g_dsum[c], (double)ts);
        atomicAdd(&g_dsq[c],  (double)tq);
    }
}

// ---------------- BN finalize (+ re-zero stats for next replay) ----------

__global__ void k_bnfin(const float* __restrict__ gamma,
                        const float* __restrict__ beta) {
    int o = threadIdx.x;
    double n = (double)NROWS;
    double mean = g_dsum[o] / n;
    double var  = g_dsq[o] / n - mean * mean;
    float sc = gamma[o] * rsqrtf((float)var + EPS);
    g_scale[o] = sc;
    g_shift[o] = beta[o] - (float)mean * sc;
    g_dsum[o] = 0.0;   // restore invariant for next graph replay
    g_dsq[o]  = 0.0;
}

// ---------------- normalize + ReLU (+ re-zero g_cnt for next replay) ------

__global__ void __launch_bounds__(256)
k_final(float* __restrict__ out) {
    int gtid = blockIdx.x * 256 + threadIdx.x;
    if (gtid < V) g_cnt[gtid] = 0;   // restore invariant (grid covers V)
    long long n4 = BVF / 4;
    for (long long i4 = gtid; i4 < n4; i4 += (long long)gridDim.x * 256) {
        long long i = i4 * 4;
        int c = (int)((i / V) & 63);
        float sc = g_scale[c], sh = g_shift[c];
        float4 v = *reinterpret_cast<const float4*>(g_acc + i);
        v.x = fmaxf(fmaf(v.x, sc, sh), 0.f);
        v.y = fmaxf(fmaf(v.y, sc, sh), 0.f);
        v.z = fmaxf(fmaf(v.z, sc, sh), 0.f);
        v.w = fmaxf(fmaf(v.w, sc, sh), 0.f);
        *reinterpret_cast<float4*>(out + i) = v;
    }
}

// ---------------- launch ----------------

extern "C" void kernel_launch(void* const* d_in, const int* in_sizes, int n_in,
                              void* d_out, int out_size) {
    const float* x      = (const float*)d_in[0];
    const int*   rows   = (const int*)  d_in[1];
    const int*   cols   = (const int*)  d_in[2];
    const float* vals   = (const float*)d_in[3];
    const float* weight = (const float*)d_in[4];
    const float* gamma  = (const float*)d_in[6];
    const float* beta   = (const float*)d_in[7];
    float* out = (float*)d_out;

    cudaFuncSetAttribute(k_gemm, cudaFuncAttributeMaxDynamicSharedMemorySize,
                         GEMM_SMEM);

    k_pre<<<NB_COUNT + NB_TRANS, 256>>>(rows, x);          // 0: count+transpose
    k_scan<<<1, 1024>>>();                                 // 1
    k_scatter<<<E / 256, 256>>>(rows, cols, vals);         // 2

    k_spmm<<<V / 8, 256>>>(0, 0, 1, 1);   // 3  <- ncu-profiled slot
    k_spmm<<<V / 8, 256>>>(1, 0, 2, 0);   // 4
    k_spmm<<<V / 8, 256>>>(2, 1, 3, 0);   // 5
    k_spmm<<<V / 8, 256>>>(3, 2, 4, 0);   // 6

    k_wprep<<<20, 256>>>(weight);                          // 7
    k_gemm<<<NROWS / 128, 256, GEMM_SMEM>>>();             // 8

    k_stats<<<B * F, 256>>>();                             // 9
    k_bnfin<<<1, 64>>>(gamma, beta);                       // 10
    k_final<<<4096, 256>>>(out);                           // 11
}